// round 11
// baseline (speedup 1.0000x reference)
#include <cuda_runtime.h>
#include <cuda_fp16.h>
#include <math.h>
#include <stdint.h>

#define S_LEN 2048
#define DMODEL 768
#define NHEAD 12
#define HDIM 64
#define FFN 3072
#define NLAYER 2

// ---------------- scratch ----------------
__device__ float  g_x  [S_LEN * DMODEL];
__device__ __half g_h  [S_LEN * DMODEL];
__device__ __half g_qkv[S_LEN * 3 * DMODEL];
__device__ __half g_att[S_LEN * DMODEL];
__device__ __half g_ffn[S_LEN * FFN];
#define WT_LAYER 7077888
__device__ __half g_wt [NLAYER * WT_LAYER];

// ---------------- ptx helpers (baseline ISA only) ----------------
__device__ __forceinline__ uint32_t smem_u32(const void* p) {
    uint32_t a;
    asm("{ .reg .u64 t; cvta.to.shared.u64 t, %1; cvt.u32.u64 %0, t; }" : "=r"(a) : "l"(p));
    return a;
}
__device__ __forceinline__ void cp16(uint32_t s, const void* g) {
    asm volatile("cp.async.cg.shared.global [%0], [%1], 16;" :: "r"(s), "l"(g));
}
__device__ __forceinline__ void cp_commit() { asm volatile("cp.async.commit_group;" ::: "memory"); }
__device__ __forceinline__ void cp_wait1()  { asm volatile("cp.async.wait_group 1;" ::: "memory"); }
__device__ __forceinline__ void cp_wait0()  { asm volatile("cp.async.wait_group 0;" ::: "memory"); }

__device__ __forceinline__ void ldsm4(uint32_t* r, uint32_t addr) {
    asm volatile("ldmatrix.sync.aligned.m8n8.x4.shared.b16 {%0,%1,%2,%3}, [%4];"
        : "=r"(r[0]), "=r"(r[1]), "=r"(r[2]), "=r"(r[3]) : "r"(addr));
}
__device__ __forceinline__ void ldsm4t(uint32_t* r, uint32_t addr) {
    asm volatile("ldmatrix.sync.aligned.m8n8.x4.trans.shared.b16 {%0,%1,%2,%3}, [%4];"
        : "=r"(r[0]), "=r"(r[1]), "=r"(r[2]), "=r"(r[3]) : "r"(addr));
}
__device__ __forceinline__ void mma16816(float* c, const uint32_t* a, const uint32_t* b) {
    asm volatile(
        "mma.sync.aligned.m16n8k16.row.col.f32.f16.f16.f32 "
        "{%0,%1,%2,%3}, {%4,%5,%6,%7}, {%8,%9}, {%0,%1,%2,%3};"
        : "+f"(c[0]), "+f"(c[1]), "+f"(c[2]), "+f"(c[3])
        : "r"(a[0]), "r"(a[1]), "r"(a[2]), "r"(a[3]), "r"(b[0]), "r"(b[1]));
}
__device__ __forceinline__ float fexp2(float x) {
    float y;
    asm("ex2.approx.ftz.f32 %0, %1;" : "=f"(y) : "f"(x));
    return y;
}

// ---------------- fused weight transpose + fp16 convert ----------------
#define OQKV 0
#define OOUT 1769472
#define OW1  2359296
#define OW2  4718592
__global__ __launch_bounds__(256)
void wconv_all_kernel(const float* __restrict__ qkv_w, const float* __restrict__ out_w,
                      const float* __restrict__ w1, const float* __restrict__ w2,
                      __half* __restrict__ wt)
{
    __shared__ float t[32][33];
    int bid = blockIdx.x;
    int layer = bid / 6912;
    int tIdx = bid % 6912;
    const float* W;
    __half* D;
    int K, N, nx;
    __half* wl = wt + (size_t)layer * WT_LAYER;
    if (tIdx < 1728)      { W = qkv_w + (size_t)layer * 768 * 2304; D = wl + OQKV; K = 768;  N = 2304; nx = 72; }
    else if (tIdx < 2304) { tIdx -= 1728; W = out_w + (size_t)layer * 768 * 768;  D = wl + OOUT; K = 768;  N = 768;  nx = 24; }
    else if (tIdx < 4608) { tIdx -= 2304; W = w1 + (size_t)layer * 768 * 3072;    D = wl + OW1;  K = 768;  N = 3072; nx = 96; }
    else                  { tIdx -= 4608; W = w2 + (size_t)layer * 3072 * 768;    D = wl + OW2;  K = 3072; N = 768;  nx = 24; }
    int n0 = (tIdx % nx) * 32, k0 = (tIdx / nx) * 32;
    int tx = threadIdx.x, ty = threadIdx.y;
    #pragma unroll
    for (int i = 0; i < 32; i += 8)
        t[ty + i][tx] = W[(size_t)(k0 + ty + i) * N + n0 + tx];
    __syncthreads();
    #pragma unroll
    for (int i = 0; i < 32; i += 8)
        D[(size_t)(n0 + ty + i) * K + k0 + tx] = __float2half(t[tx][ty + i]);
}

// ---------------- layernorm common ----------------
__device__ __forceinline__ float block_reduce_sum(float v, float* red)
{
    #pragma unroll
    for (int o = 16; o > 0; o >>= 1) v += __shfl_xor_sync(0xffffffffu, v, o);
    __syncthreads();
    if ((threadIdx.x & 31) == 0) red[threadIdx.x >> 5] = v;
    __syncthreads();
    float t = 0.f;
    #pragma unroll
    for (int i = 0; i < 8; i++) t += red[i];
    return t;
}

// fused embed + LN1 (layer 0): x = emb[idx]+pe; h = LN(x)
__global__ __launch_bounds__(256)
void embed_ln_kernel(const int* __restrict__ idx, const float* __restrict__ emb,
                     const float* __restrict__ pe, const float* __restrict__ s,
                     const float* __restrict__ b, float* __restrict__ x,
                     __half* __restrict__ o)
{
    __shared__ float red[8];
    int row = blockIdx.x;
    int tid = threadIdx.x;
    int tok = idx[row];
    const float* ep = emb + (size_t)tok * DMODEL;
    const float* pp = pe + (size_t)row * DMODEL;
    float v0 = ep[tid] + pp[tid];
    float v1 = ep[tid + 256] + pp[tid + 256];
    float v2 = ep[tid + 512] + pp[tid + 512];
    float* xp = x + (size_t)row * DMODEL;
    xp[tid] = v0; xp[tid + 256] = v1; xp[tid + 512] = v2;
    float mean = block_reduce_sum(v0 + v1 + v2, red) * (1.0f / DMODEL);
    float d0 = v0 - mean, d1 = v1 - mean, d2 = v2 - mean;
    float var = block_reduce_sum(d0 * d0 + d1 * d1 + d2 * d2, red) * (1.0f / DMODEL);
    float r = rsqrtf(var + 1e-5f);
    __half* op = o + (size_t)row * DMODEL;
    op[tid]       = __float2half(d0 * r * s[tid]       + b[tid]);
    op[tid + 256] = __float2half(d1 * r * s[tid + 256] + b[tid + 256]);
    op[tid + 512] = __float2half(d2 * r * s[tid + 512] + b[tid + 512]);
}

__global__ __launch_bounds__(256)
void ln_kernel(const float* __restrict__ x, const float* __restrict__ s,
               const float* __restrict__ b, __half* __restrict__ o)
{
    __shared__ float red[8];
    int row = blockIdx.x;
    int tid = threadIdx.x;
    const float* xp = x + (size_t)row * DMODEL;
    float v0 = xp[tid], v1 = xp[tid + 256], v2 = xp[tid + 512];
    float mean = block_reduce_sum(v0 + v1 + v2, red) * (1.0f / DMODEL);
    float d0 = v0 - mean, d1 = v1 - mean, d2 = v2 - mean;
    float var = block_reduce_sum(d0 * d0 + d1 * d1 + d2 * d2, red) * (1.0f / DMODEL);
    float r = rsqrtf(var + 1e-5f);
    __half* op = o + (size_t)row * DMODEL;
    op[tid]       = __float2half(d0 * r * s[tid]       + b[tid]);
    op[tid + 256] = __float2half(d1 * r * s[tid + 256] + b[tid + 256]);
    op[tid + 512] = __float2half(d2 * r * s[tid + 512] + b[tid + 512]);
}

// ---------------- fp16 HMMA GEMM: C[M,N] = A[M,K] @ Bt[N,K]^T ----------------
// Tile 64x64, 4 warps (warp tile 32x32), 3-stage cp.async, one barrier per slab.
// MODE 0: +bias (half out)  MODE 1: gelu(+bias) (half out)  MODE 2: +bias+resid (float out)
#define SWC(c, r) ((((c) ^ ((r) & 7))) << 4)
template<int MODE>
__global__ __launch_bounds__(128)
void hgemm_kernel(const __half* __restrict__ A, const __half* __restrict__ Bt,
                  const float* __restrict__ bias, const float* __restrict__ resid,
                  void* __restrict__ Cv, int M, int N, int K)
{
    extern __shared__ __align__(1024) char smem[];
    constexpr int STG = 128 * 128;               // 16KB per stage (A 8K + B 8K)

    uint32_t sb = smem_u32(smem);
    int tid = threadIdx.x, lane = tid & 31, warp = tid >> 5;
    int warp_m = warp & 1, warp_n = warp >> 1;
    int m0 = blockIdx.y * 64, n0 = blockIdx.x * 64;
    int mbase = warp_m * 32, nbase = warp_n * 32;

    const __half* Ag0 = A + (size_t)m0 * K;
    const __half* Bg0 = Bt + (size_t)n0 * K;
    int nslab = K >> 6;

    auto load_slab = [&](int s, int b) {
        uint32_t ab = sb + b * STG;
        uint32_t bb = ab + 8192;
        const __half* Ap = Ag0 + s * 64;
        const __half* Bp = Bg0 + s * 64;
        #pragma unroll
        for (int i = 0; i < 4; i++) {
            int idx = tid + 128 * i;
            int r = idx >> 3, c = idx & 7;
            cp16(ab + r * 128 + SWC(c, r), Ap + (size_t)r * K + c * 8);
        }
        #pragma unroll
        for (int i = 0; i < 4; i++) {
            int idx = tid + 128 * i;
            int r = idx >> 3, c = idx & 7;
            cp16(bb + r * 128 + SWC(c, r), Bp + (size_t)r * K + c * 8);
        }
        cp_commit();
    };

    float acc[2][4][4];
    #pragma unroll
    for (int mt = 0; mt < 2; mt++)
        #pragma unroll
        for (int nt = 0; nt < 4; nt++)
            #pragma unroll
            for (int i = 0; i < 4; i++) acc[mt][nt][i] = 0.f;

    load_slab(0, 0);
    load_slab(1, 1);

    int lrA = lane & 15, lcA = lane >> 4;
    int lrB = ((lane >> 4) << 3) + (lane & 7), lcB = (lane >> 3) & 1;

    int buf = 0;
    for (int s = 0; s < nslab; s++) {
        if (s + 1 < nslab) cp_wait1(); else cp_wait0();
        __syncthreads();                          // slab s visible; compute s-1 closed
        if (s + 2 < nslab) {
            int nb = buf + 2; if (nb >= 3) nb -= 3;
            load_slab(s + 2, nb);
        }
        uint32_t ab = sb + buf * STG;
        uint32_t bb = ab + 8192;

        #pragma unroll
        for (int k = 0; k < 4; k++) {
            uint32_t a[2][4], bq[2][4];
            #pragma unroll
            for (int mt = 0; mt < 2; mt++) {
                int r = mbase + mt * 16 + lrA;
                int c = k * 2 + lcA;
                ldsm4(a[mt], ab + r * 128 + SWC(c, r));
            }
            #pragma unroll
            for (int p = 0; p < 2; p++) {
                int r = nbase + p * 16 + lrB;
                int c = k * 2 + lcB;
                ldsm4(bq[p], bb + r * 128 + SWC(c, r));
            }
            #pragma unroll
            for (int mt = 0; mt < 2; mt++)
                #pragma unroll
                for (int nt = 0; nt < 4; nt++)
                    mma16816(acc[mt][nt], a[mt], bq[nt >> 1] + 2 * (nt & 1));
        }
        if (++buf == 3) buf = 0;
    }

    int row4 = lane >> 2, col2 = (lane & 3) * 2;
    #pragma unroll
    for (int mt = 0; mt < 2; mt++) {
        #pragma unroll
        for (int nt = 0; nt < 4; nt++) {
            int r0 = m0 + mbase + mt * 16 + row4;
            int cc = n0 + nbase + nt * 8 + col2;
            float2 bb = *(const float2*)(bias + cc);
            float v0 = acc[mt][nt][0] + bb.x, v1 = acc[mt][nt][1] + bb.y;
            float v2 = acc[mt][nt][2] + bb.x, v3 = acc[mt][nt][3] + bb.y;
            if (MODE == 1) {
                v0 = 0.5f * v0 * (1.0f + erff(v0 * 0.70710678118654752f));
                v1 = 0.5f * v1 * (1.0f + erff(v1 * 0.70710678118654752f));
                v2 = 0.5f * v2 * (1.0f + erff(v2 * 0.70710678118654752f));
                v3 = 0.5f * v3 * (1.0f + erff(v3 * 0.70710678118654752f));
            }
            if (MODE == 2) {
                float2 ra = *(const float2*)(resid + (size_t)r0 * N + cc);
                float2 rb = *(const float2*)(resid + (size_t)(r0 + 8) * N + cc);
                v0 += ra.x; v1 += ra.y; v2 += rb.x; v3 += rb.y;
                float* Cp = (float*)Cv;
                float2 o0 = {v0, v1}, o1 = {v2, v3};
                *(float2*)(Cp + (size_t)r0 * N + cc) = o0;
                *(float2*)(Cp + (size_t)(r0 + 8) * N + cc) = o1;
            } else {
                __half* Cp = (__half*)Cv;
                *(__half2*)(Cp + (size_t)r0 * N + cc)       = __floats2half2_rn(v0, v1);
                *(__half2*)(Cp + (size_t)(r0 + 8) * N + cc) = __floats2half2_rn(v2, v3);
            }
        }
    }
}

// ---------------- tensor-core causal flash attention (3-stage) ----------------
// CTA: 64 queries x 1 head, 4 warps. smem: Q [0,8K); stage st in {0,1,2}: K at 8K+st*16K, V +8K.
#define ATT_SCALE 0.18033688f   // 0.125 * log2(e); softmax in exp2 domain
__global__ __launch_bounds__(128)
void fattn_kernel(const __half* __restrict__ qkv, __half* __restrict__ o)
{
    extern __shared__ __align__(1024) char smem[];
    uint32_t sb = smem_u32(smem);
    int h = blockIdx.y;
    int qblk = gridDim.x - 1 - blockIdx.x;
    int q0 = qblk * 64;
    int tid = threadIdx.x, lane = tid & 31, warp = tid >> 5;
    int mbase = warp * 16;
    int ntile = qblk + 1;

    auto loadKV = [&](int kt, int st) {
        uint32_t kb = sb + 8192 + st * 16384;
        uint32_t vb = kb + 8192;
        #pragma unroll
        for (int i = 0; i < 4; i++) {
            int idx = tid + 128 * i;
            int r = idx >> 3, c = idx & 7;
            const __half* kp = qkv + (size_t)(kt + r) * 2304 + 768 + h * 64 + c * 8;
            cp16(kb + r * 128 + SWC(c, r), kp);
            cp16(vb + r * 128 + SWC(c, r), kp + 768);
        }
        cp_commit();
    };

    #pragma unroll
    for (int i = 0; i < 4; i++) {
        int idx = tid + 128 * i;
        int r = idx >> 3, c = idx & 7;
        cp16(sb + r * 128 + SWC(c, r), qkv + (size_t)(q0 + r) * 2304 + h * 64 + c * 8);
    }
    loadKV(0, 0);                       // group 0 = Q + KV0
    if (ntile > 1) loadKV(64, 1);       // group 1 = KV1

    uint32_t qf[4][4];
    float oacc[8][4];
    #pragma unroll
    for (int nt = 0; nt < 8; nt++)
        #pragma unroll
        for (int i = 0; i < 4; i++) oacc[nt][i] = 0.f;
    float m0 = -1e30f, m1 = -1e30f, l0 = 0.f, l1 = 0.f;

    int lrA = lane & 15, lcA = lane >> 4;
    int lrB = ((lane >> 4) << 3) + (lane & 7), lcB = (lane >> 3) & 1;
    int qrow0 = q0 + mbase + (lane >> 2);

    int buf = 0;
    for (int it = 0; it < ntile; it++) {
        if (it + 1 < ntile) cp_wait1(); else cp_wait0();
        __syncthreads();
        if (it + 2 < ntile) {
            int nb = buf + 2; if (nb >= 3) nb -= 3;
            loadKV((it + 2) * 64, nb);
        }
        if (it == 0) {
            #pragma unroll
            for (int ks = 0; ks < 4; ks++) {
                int r = mbase + lrA, c = ks * 2 + lcA;
                ldsm4(qf[ks], sb + r * 128 + SWC(c, r));
            }
        }
        uint32_t kb = sb + 8192 + buf * 16384;
        uint32_t vb = kb + 8192;

        // ---- scores = Q @ K^T ----
        float sc[8][4];
        #pragma unroll
        for (int nt = 0; nt < 8; nt++)
            #pragma unroll
            for (int i = 0; i < 4; i++) sc[nt][i] = 0.f;
        #pragma unroll
        for (int ks = 0; ks < 4; ks++) {
            uint32_t kf[4][4];
            #pragma unroll
            for (int p = 0; p < 4; p++) {
                int r = p * 16 + lrB, c = ks * 2 + lcB;
                ldsm4(kf[p], kb + r * 128 + SWC(c, r));
            }
            #pragma unroll
            for (int nt = 0; nt < 8; nt++)
                mma16816(sc[nt], qf[ks], kf[nt >> 1] + 2 * (nt & 1));
        }

        // ---- scale (exp2 domain) + causal mask on diagonal tile ----
        if (it == ntile - 1) {
            #pragma unroll
            for (int nt = 0; nt < 8; nt++) {
                int kc = it * 64 + nt * 8 + (lane & 3) * 2;
                sc[nt][0] = (kc     <= qrow0)     ? sc[nt][0] * ATT_SCALE : -1e30f;
                sc[nt][1] = (kc + 1 <= qrow0)     ? sc[nt][1] * ATT_SCALE : -1e30f;
                sc[nt][2] = (kc     <= qrow0 + 8) ? sc[nt][2] * ATT_SCALE : -1e30f;
                sc[nt][3] = (kc + 1 <= qrow0 + 8) ? sc[nt][3] * ATT_SCALE : -1e30f;
            }
        } else {
            #pragma unroll
            for (int nt = 0; nt < 8; nt++) {
                sc[nt][0] *= ATT_SCALE; sc[nt][1] *= ATT_SCALE;
                sc[nt][2] *= ATT_SCALE; sc[nt][3] *= ATT_SCALE;
            }
        }

        // ---- online softmax (tile-granular, exp2) ----
        float mx0 = sc[0][0], mx1 = sc[0][2];
        #pragma unroll
        for (int nt = 0; nt < 8; nt++) {
            mx0 = fmaxf(mx0, fmaxf(sc[nt][0], sc[nt][1]));
            mx1 = fmaxf(mx1, fmaxf(sc[nt][2], sc[nt][3]));
        }
        mx0 = fmaxf(mx0, __shfl_xor_sync(0xffffffffu, mx0, 1));
        mx0 = fmaxf(mx0, __shfl_xor_sync(0xffffffffu, mx0, 2));
        mx1 = fmaxf(mx1, __shfl_xor_sync(0xffffffffu, mx1, 1));
        mx1 = fmaxf(mx1, __shfl_xor_sync(0xffffffffu, mx1, 2));
        float m0n = fmaxf(m0, mx0), m1n = fmaxf(m1, mx1);
        float a0 = fexp2(m0 - m0n), a1 = fexp2(m1 - m1n);
        m0 = m0n; m1 = m1n;

        float s0 = 0.f, s1 = 0.f;
        uint32_t pf[4][4];
        #pragma unroll
        for (int nt = 0; nt < 8; nt++) {
            float p0 = fexp2(sc[nt][0] - m0);
            float p1 = fexp2(sc[nt][1] - m0);
            float p2 = fexp2(sc[nt][2] - m1);
            float p3 = fexp2(sc[nt][3] - m1);
            s0 += p0 + p1; s1 += p2 + p3;
            __half2 h01 = __floats2half2_rn(p0, p1);
            __half2 h23 = __floats2half2_rn(p2, p3);
            pf[nt >> 1][(nt & 1) * 2 + 0] = *(uint32_t*)&h01;
            pf[nt >> 1][(nt & 1) * 2 + 1] = *(uint32_t*)&h23;
        }
        l0 = l0 * a0 + s0;
        l1 = l1 * a1 + s1;
        #pragma unroll
        for (int nt = 0; nt < 8; nt++) {
            oacc[nt][0] *= a0; oacc[nt][1] *= a0;
            oacc[nt][2] *= a1; oacc[nt][3] *= a1;
        }

        // ---- O += P @ V ----
        #pragma unroll
        for (int ks = 0; ks < 4; ks++) {
            uint32_t vf[4][4];
            #pragma unroll
            for (int j = 0; j < 4; j++) {
                int r = ks * 16 + ((lane >> 3) & 1) * 8 + (lane & 7);
                int c = j * 2 + (lane >> 4);
                ldsm4t(vf[j], vb + r * 128 + SWC(c, r));
            }
            #pragma unroll
            for (int j = 0; j < 4; j++) {
                mma16816(oacc[2 * j],     pf[ks], vf[j]);
                mma16816(oacc[2 * j + 1], pf[ks], vf[j] + 2);
            }
        }
        if (++buf == 3) buf = 0;
    }

    l0 += __shfl_xor_sync(0xffffffffu, l0, 1);
    l0 += __shfl_xor_sync(0xffffffffu, l0, 2);
    l1 += __shfl_xor_sync(0xffffffffu, l1, 1);
    l1 += __shfl_xor_sync(0xffffffffu, l1, 2);
    float inv0 = 1.0f / l0, inv1 = 1.0f / l1;
    #pragma unroll
    for (int nt = 0; nt < 8; nt++) {
        int cc = h * 64 + nt * 8 + (lane & 3) * 2;
        *(__half2*)(o + (size_t)qrow0 * DMODEL + cc) =
            __floats2half2_rn(oacc[nt][0] * inv0, oacc[nt][1] * inv0);
        *(__half2*)(o + (size_t)(qrow0 + 8) * DMODEL + cc) =
            __floats2half2_rn(oacc[nt][2] * inv1, oacc[nt][3] * inv1);
    }
}

// ---------------- host orchestration ----------------
extern "C" void kernel_launch(void* const* d_in, const int* in_sizes, int n_in,
                              void* d_out, int out_size)
{
    const int*   idx    = (const int*)  d_in[0];
    const float* temb   = (const float*)d_in[1];
    const float* pe     = (const float*)d_in[2];
    const float* qkv_w  = (const float*)d_in[3];
    const float* qkv_b  = (const float*)d_in[4];
    const float* out_w  = (const float*)d_in[5];
    const float* out_b  = (const float*)d_in[6];
    const float* ln1_s  = (const float*)d_in[7];
    const float* ln1_b  = (const float*)d_in[8];
    const float* ln2_s  = (const float*)d_in[9];
    const float* ln2_b  = (const float*)d_in[10];
    const float* w1     = (const float*)d_in[11];
    const float* b1     = (const float*)d_in[12];
    const float* w2     = (const float*)d_in[13];
    const float* b2     = (const float*)d_in[14];
    float* out = (float*)d_out;

    float* x;
    __half *hbuf, *qkvb, *att, *ffn, *wt;
    cudaGetSymbolAddress((void**)&x,    g_x);
    cudaGetSymbolAddress((void**)&hbuf, g_h);
    cudaGetSymbolAddress((void**)&qkvb, g_qkv);
    cudaGetSymbolAddress((void**)&att,  g_att);
    cudaGetSymbolAddress((void**)&ffn,  g_ffn);
    cudaGetSymbolAddress((void**)&wt,   g_wt);

    constexpr int SMB   = 3 * 128 * 128;           // 49152
    constexpr int SMATT = 8192 + 3 * 16384;        // 57344
    cudaFuncSetAttribute(hgemm_kernel<0>, cudaFuncAttributeMaxDynamicSharedMemorySize, SMB);
    cudaFuncSetAttribute(hgemm_kernel<1>, cudaFuncAttributeMaxDynamicSharedMemorySize, SMB);
    cudaFuncSetAttribute(hgemm_kernel<2>, cudaFuncAttributeMaxDynamicSharedMemorySize, SMB);
    cudaFuncSetAttribute(fattn_kernel,    cudaFuncAttributeMaxDynamicSharedMemorySize, SMATT);

    wconv_all_kernel<<<2 * 6912, dim3(32, 8)>>>(qkv_w, out_w, w1, w2, wt);
    embed_ln_kernel<<<S_LEN, 256>>>(idx, temb, pe, ln1_s, ln1_b, x, hbuf);

    for (int l = 0; l < NLAYER; l++) {
        __half* wl = wt + (size_t)l * WT_LAYER;
        const float* lqkv_b = qkv_b + (size_t)l * 3 * DMODEL;
        const float* lout_b = out_b + (size_t)l * DMODEL;
        const float* lb1    = b1 + (size_t)l * FFN;
        const float* lb2    = b2 + (size_t)l * DMODEL;

        if (l > 0)
            ln_kernel<<<S_LEN, 256>>>(x, ln1_s + l * DMODEL, ln1_b + l * DMODEL, hbuf);
        hgemm_kernel<0><<<dim3(3 * DMODEL / 64, S_LEN / 64), 128, SMB>>>(
            hbuf, wl + OQKV, lqkv_b, nullptr, qkvb, S_LEN, 3 * DMODEL, DMODEL);
        fattn_kernel<<<dim3(S_LEN / 64, NHEAD), 128, SMATT>>>(qkvb, att);
        hgemm_kernel<2><<<dim3(DMODEL / 64, S_LEN / 64), 128, SMB>>>(
            att, wl + OOUT, lout_b, x, x, S_LEN, DMODEL, DMODEL);
        ln_kernel<<<S_LEN, 256>>>(x, ln2_s + l * DMODEL, ln2_b + l * DMODEL, hbuf);
        hgemm_kernel<1><<<dim3(FFN / 64, S_LEN / 64), 128, SMB>>>(
            hbuf, wl + OW1, lb1, nullptr, ffn, S_LEN, FFN, DMODEL);
        float* dst = (l == NLAYER - 1) ? out : x;
        hgemm_kernel<2><<<dim3(DMODEL / 64, S_LEN / 64), 128, SMB>>>(
            ffn, wl + OW2, lb2, x, dst, S_LEN, DMODEL, FFN);
    }
}

// round 12
// speedup vs baseline: 1.4948x; 1.4948x over previous
#include <cuda_runtime.h>
#include <cuda_fp16.h>
#include <math.h>
#include <stdint.h>

#define S_LEN 2048
#define DMODEL 768
#define NHEAD 12
#define HDIM 64
#define FFN 3072
#define NLAYER 2

// ---------------- scratch ----------------
__device__ float  g_x  [S_LEN * DMODEL];
__device__ __half g_h  [S_LEN * DMODEL];
__device__ __half g_qkv[S_LEN * 3 * DMODEL];
__device__ __half g_att[S_LEN * DMODEL];
__device__ __half g_ffn[S_LEN * FFN];
#define WT_LAYER 7077888
__device__ __half g_wt [NLAYER * WT_LAYER];

// ---------------- ptx helpers (baseline ISA only) ----------------
__device__ __forceinline__ uint32_t smem_u32(const void* p) {
    uint32_t a;
    asm("{ .reg .u64 t; cvta.to.shared.u64 t, %1; cvt.u32.u64 %0, t; }" : "=r"(a) : "l"(p));
    return a;
}
__device__ __forceinline__ void cp16(uint32_t s, const void* g) {
    asm volatile("cp.async.cg.shared.global [%0], [%1], 16;" :: "r"(s), "l"(g));
}
__device__ __forceinline__ void cp_commit() { asm volatile("cp.async.commit_group;" ::: "memory"); }
__device__ __forceinline__ void cp_wait1()  { asm volatile("cp.async.wait_group 1;" ::: "memory"); }
__device__ __forceinline__ void cp_wait0()  { asm volatile("cp.async.wait_group 0;" ::: "memory"); }

__device__ __forceinline__ void ldsm4(uint32_t* r, uint32_t addr) {
    asm volatile("ldmatrix.sync.aligned.m8n8.x4.shared.b16 {%0,%1,%2,%3}, [%4];"
        : "=r"(r[0]), "=r"(r[1]), "=r"(r[2]), "=r"(r[3]) : "r"(addr));
}
__device__ __forceinline__ void ldsm4t(uint32_t* r, uint32_t addr) {
    asm volatile("ldmatrix.sync.aligned.m8n8.x4.trans.shared.b16 {%0,%1,%2,%3}, [%4];"
        : "=r"(r[0]), "=r"(r[1]), "=r"(r[2]), "=r"(r[3]) : "r"(addr));
}
__device__ __forceinline__ void mma16816(float* c, const uint32_t* a, const uint32_t* b) {
    asm volatile(
        "mma.sync.aligned.m16n8k16.row.col.f32.f16.f16.f32 "
        "{%0,%1,%2,%3}, {%4,%5,%6,%7}, {%8,%9}, {%0,%1,%2,%3};"
        : "+f"(c[0]), "+f"(c[1]), "+f"(c[2]), "+f"(c[3])
        : "r"(a[0]), "r"(a[1]), "r"(a[2]), "r"(a[3]), "r"(b[0]), "r"(b[1]));
}
__device__ __forceinline__ float fexp2(float x) {
    float y;
    asm("ex2.approx.ftz.f32 %0, %1;" : "=f"(y) : "f"(x));
    return y;
}

// ---------------- fused weight transpose + fp16 convert ----------------
#define OQKV 0
#define OOUT 1769472
#define OW1  2359296
#define OW2  4718592
__global__ __launch_bounds__(256)
void wconv_all_kernel(const float* __restrict__ qkv_w, const float* __restrict__ out_w,
                      const float* __restrict__ w1, const float* __restrict__ w2,
                      __half* __restrict__ wt)
{
    __shared__ float t[32][33];
    int bid = blockIdx.x;
    int layer = bid / 6912;
    int tIdx = bid % 6912;
    const float* W;
    __half* D;
    int K, N, nx;
    __half* wl = wt + (size_t)layer * WT_LAYER;
    if (tIdx < 1728)      { W = qkv_w + (size_t)layer * 768 * 2304; D = wl + OQKV; K = 768;  N = 2304; nx = 72; }
    else if (tIdx < 2304) { tIdx -= 1728; W = out_w + (size_t)layer * 768 * 768;  D = wl + OOUT; K = 768;  N = 768;  nx = 24; }
    else if (tIdx < 4608) { tIdx -= 2304; W = w1 + (size_t)layer * 768 * 3072;    D = wl + OW1;  K = 768;  N = 3072; nx = 96; }
    else                  { tIdx -= 4608; W = w2 + (size_t)layer * 3072 * 768;    D = wl + OW2;  K = 3072; N = 768;  nx = 24; }
    int n0 = (tIdx % nx) * 32, k0 = (tIdx / nx) * 32;
    int tx = threadIdx.x, ty = threadIdx.y;
    #pragma unroll
    for (int i = 0; i < 32; i += 8)
        t[ty + i][tx] = W[(size_t)(k0 + ty + i) * N + n0 + tx];
    __syncthreads();
    #pragma unroll
    for (int i = 0; i < 32; i += 8)
        D[(size_t)(n0 + ty + i) * K + k0 + tx] = __float2half(t[tx][ty + i]);
}

// ---------------- layernorm common ----------------
__device__ __forceinline__ float block_reduce_sum(float v, float* red)
{
    #pragma unroll
    for (int o = 16; o > 0; o >>= 1) v += __shfl_xor_sync(0xffffffffu, v, o);
    __syncthreads();
    if ((threadIdx.x & 31) == 0) red[threadIdx.x >> 5] = v;
    __syncthreads();
    float t = 0.f;
    #pragma unroll
    for (int i = 0; i < 8; i++) t += red[i];
    return t;
}

// fused embed + LN1 (layer 0): x = emb[idx]+pe; h = LN(x)
__global__ __launch_bounds__(256)
void embed_ln_kernel(const int* __restrict__ idx, const float* __restrict__ emb,
                     const float* __restrict__ pe, const float* __restrict__ s,
                     const float* __restrict__ b, float* __restrict__ x,
                     __half* __restrict__ o)
{
    __shared__ float red[8];
    int row = blockIdx.x;
    int tid = threadIdx.x;
    int tok = idx[row];
    const float* ep = emb + (size_t)tok * DMODEL;
    const float* pp = pe + (size_t)row * DMODEL;
    float v0 = ep[tid] + pp[tid];
    float v1 = ep[tid + 256] + pp[tid + 256];
    float v2 = ep[tid + 512] + pp[tid + 512];
    float* xp = x + (size_t)row * DMODEL;
    xp[tid] = v0; xp[tid + 256] = v1; xp[tid + 512] = v2;
    float mean = block_reduce_sum(v0 + v1 + v2, red) * (1.0f / DMODEL);
    float d0 = v0 - mean, d1 = v1 - mean, d2 = v2 - mean;
    float var = block_reduce_sum(d0 * d0 + d1 * d1 + d2 * d2, red) * (1.0f / DMODEL);
    float r = rsqrtf(var + 1e-5f);
    __half* op = o + (size_t)row * DMODEL;
    op[tid]       = __float2half(d0 * r * s[tid]       + b[tid]);
    op[tid + 256] = __float2half(d1 * r * s[tid + 256] + b[tid + 256]);
    op[tid + 512] = __float2half(d2 * r * s[tid + 512] + b[tid + 512]);
}

__global__ __launch_bounds__(256)
void ln_kernel(const float* __restrict__ x, const float* __restrict__ s,
               const float* __restrict__ b, __half* __restrict__ o)
{
    __shared__ float red[8];
    int row = blockIdx.x;
    int tid = threadIdx.x;
    const float* xp = x + (size_t)row * DMODEL;
    float v0 = xp[tid], v1 = xp[tid + 256], v2 = xp[tid + 512];
    float mean = block_reduce_sum(v0 + v1 + v2, red) * (1.0f / DMODEL);
    float d0 = v0 - mean, d1 = v1 - mean, d2 = v2 - mean;
    float var = block_reduce_sum(d0 * d0 + d1 * d1 + d2 * d2, red) * (1.0f / DMODEL);
    float r = rsqrtf(var + 1e-5f);
    __half* op = o + (size_t)row * DMODEL;
    op[tid]       = __float2half(d0 * r * s[tid]       + b[tid]);
    op[tid + 256] = __float2half(d1 * r * s[tid + 256] + b[tid + 256]);
    op[tid + 512] = __float2half(d2 * r * s[tid + 512] + b[tid + 512]);
}

// ---------------- fp16 HMMA GEMM: C[M,N] = A[M,K] @ Bt[N,K]^T ----------------
// Tile 64 x BN, warp tile 32x32, threads = 2*BN, double-buffered cp.async.  (round-9 config)
// MODE 0: +bias (half out)  MODE 1: gelu(+bias) (half out)  MODE 2: +bias+resid (float out)
#define SWC(c, r) ((((c) ^ ((r) & 7))) << 4)
template<int BN, int MODE>
__global__ __launch_bounds__(2 * BN)
void hgemm_kernel(const __half* __restrict__ A, const __half* __restrict__ Bt,
                  const float* __restrict__ bias, const float* __restrict__ resid,
                  void* __restrict__ Cv, int M, int N, int K)
{
    extern __shared__ __align__(1024) char smem[];
    constexpr int THR = 2 * BN;
    constexpr int ABYTES = 64 * 128;
    constexpr int STG = (64 + BN) * 128;

    uint32_t sb = smem_u32(smem);
    int tid = threadIdx.x, lane = tid & 31, warp = tid >> 5;
    int warp_m = warp & 1, warp_n = warp >> 1;
    int m0 = blockIdx.y * 64, n0 = blockIdx.x * BN;
    int mbase = warp_m * 32, nbase = warp_n * 32;

    const __half* Ag0 = A + (size_t)m0 * K;
    const __half* Bg0 = Bt + (size_t)n0 * K;
    int nslab = K >> 6;

    auto load_slab = [&](int s, int b) {
        uint32_t ab = sb + b * STG;
        uint32_t bb = ab + ABYTES;
        const __half* Ap = Ag0 + s * 64;
        const __half* Bp = Bg0 + s * 64;
        #pragma unroll
        for (int i = 0; i < 512 / THR; i++) {
            int idx = tid + THR * i;
            int r = idx >> 3, c = idx & 7;
            cp16(ab + r * 128 + SWC(c, r), Ap + (size_t)r * K + c * 8);
        }
        #pragma unroll
        for (int i = 0; i < (8 * BN) / THR; i++) {
            int idx = tid + THR * i;
            int r = idx >> 3, c = idx & 7;
            cp16(bb + r * 128 + SWC(c, r), Bp + (size_t)r * K + c * 8);
        }
        cp_commit();
    };

    float acc[2][4][4];
    #pragma unroll
    for (int mt = 0; mt < 2; mt++)
        #pragma unroll
        for (int nt = 0; nt < 4; nt++)
            #pragma unroll
            for (int i = 0; i < 4; i++) acc[mt][nt][i] = 0.f;

    load_slab(0, 0);

    int lrA = lane & 15, lcA = lane >> 4;
    int lrB = ((lane >> 4) << 3) + (lane & 7), lcB = (lane >> 3) & 1;

    for (int s = 0; s < nslab; s++) {
        if (s + 1 < nslab) { load_slab(s + 1, (s + 1) & 1); cp_wait1(); }
        else               { cp_wait0(); }
        __syncthreads();

        uint32_t ab = sb + (s & 1) * STG;
        uint32_t bb = ab + ABYTES;

        #pragma unroll
        for (int k = 0; k < 4; k++) {
            uint32_t a[2][4], bq[2][4];
            #pragma unroll
            for (int mt = 0; mt < 2; mt++) {
                int r = mbase + mt * 16 + lrA;
                int c = k * 2 + lcA;
                ldsm4(a[mt], ab + r * 128 + SWC(c, r));
            }
            #pragma unroll
            for (int p = 0; p < 2; p++) {
                int r = nbase + p * 16 + lrB;
                int c = k * 2 + lcB;
                ldsm4(bq[p], bb + r * 128 + SWC(c, r));
            }
            #pragma unroll
            for (int mt = 0; mt < 2; mt++)
                #pragma unroll
                for (int nt = 0; nt < 4; nt++)
                    mma16816(acc[mt][nt], a[mt], bq[nt >> 1] + 2 * (nt & 1));
        }
        __syncthreads();
    }

    int row4 = lane >> 2, col2 = (lane & 3) * 2;
    #pragma unroll
    for (int mt = 0; mt < 2; mt++) {
        #pragma unroll
        for (int nt = 0; nt < 4; nt++) {
            int r0 = m0 + mbase + mt * 16 + row4;
            int cc = n0 + nbase + nt * 8 + col2;
            float2 bb = *(const float2*)(bias + cc);
            float v0 = acc[mt][nt][0] + bb.x, v1 = acc[mt][nt][1] + bb.y;
            float v2 = acc[mt][nt][2] + bb.x, v3 = acc[mt][nt][3] + bb.y;
            if (MODE == 1) {
                v0 = 0.5f * v0 * (1.0f + erff(v0 * 0.70710678118654752f));
                v1 = 0.5f * v1 * (1.0f + erff(v1 * 0.70710678118654752f));
                v2 = 0.5f * v2 * (1.0f + erff(v2 * 0.70710678118654752f));
                v3 = 0.5f * v3 * (1.0f + erff(v3 * 0.70710678118654752f));
            }
            if (MODE == 2) {
                float2 ra = *(const float2*)(resid + (size_t)r0 * N + cc);
                float2 rb = *(const float2*)(resid + (size_t)(r0 + 8) * N + cc);
                v0 += ra.x; v1 += ra.y; v2 += rb.x; v3 += rb.y;
                float* Cp = (float*)Cv;
                float2 o0 = {v0, v1}, o1 = {v2, v3};
                *(float2*)(Cp + (size_t)r0 * N + cc) = o0;
                *(float2*)(Cp + (size_t)(r0 + 8) * N + cc) = o1;
            } else {
                __half* Cp = (__half*)Cv;
                *(__half2*)(Cp + (size_t)r0 * N + cc)       = __floats2half2_rn(v0, v1);
                *(__half2*)(Cp + (size_t)(r0 + 8) * N + cc) = __floats2half2_rn(v2, v3);
            }
        }
    }
}

// ---------------- tensor-core causal flash attention (round-9 2-stage + exp2) ----------------
// CTA: 64 queries x 1 head, 4 warps. smem: Q [0,8K); stage st in {0,1}: K at 8K+st*16K, V +8K.
#define ATT_SCALE 0.18033688f   // 0.125 * log2(e); softmax in exp2 domain
__global__ __launch_bounds__(128)
void fattn_kernel(const __half* __restrict__ qkv, __half* __restrict__ o)
{
    extern __shared__ __align__(1024) char smem[];
    uint32_t sb = smem_u32(smem);
    int h = blockIdx.y;
    int qblk = gridDim.x - 1 - blockIdx.x;          // heavy blocks first
    int q0 = qblk * 64;
    int tid = threadIdx.x, lane = tid & 31, warp = tid >> 5;
    int mbase = warp * 16;
    int ntile = qblk + 1;

    auto loadKV = [&](int kt, int st) {
        uint32_t kb = sb + 8192 + st * 16384;
        uint32_t vb = kb + 8192;
        #pragma unroll
        for (int i = 0; i < 4; i++) {
            int idx = tid + 128 * i;
            int r = idx >> 3, c = idx & 7;
            const __half* kp = qkv + (size_t)(kt + r) * 2304 + 768 + h * 64 + c * 8;
            cp16(kb + r * 128 + SWC(c, r), kp);
            cp16(vb + r * 128 + SWC(c, r), kp + 768);
        }
        cp_commit();
    };

    // Q tile + first KV stage in one cp.async group
    #pragma unroll
    for (int i = 0; i < 4; i++) {
        int idx = tid + 128 * i;
        int r = idx >> 3, c = idx & 7;
        cp16(sb + r * 128 + SWC(c, r), qkv + (size_t)(q0 + r) * 2304 + h * 64 + c * 8);
    }
    loadKV(0, 0);

    uint32_t qf[4][4];
    float oacc[8][4];
    #pragma unroll
    for (int nt = 0; nt < 8; nt++)
        #pragma unroll
        for (int i = 0; i < 4; i++) oacc[nt][i] = 0.f;
    float m0 = -1e30f, m1 = -1e30f, l0 = 0.f, l1 = 0.f;

    int lrA = lane & 15, lcA = lane >> 4;
    int lrB = ((lane >> 4) << 3) + (lane & 7), lcB = (lane >> 3) & 1;
    int qrow0 = q0 + mbase + (lane >> 2);

    for (int it = 0; it < ntile; it++) {
        if (it + 1 < ntile) { loadKV((it + 1) * 64, (it + 1) & 1); cp_wait1(); }
        else                { cp_wait0(); }
        __syncthreads();
        if (it == 0) {
            #pragma unroll
            for (int ks = 0; ks < 4; ks++) {
                int r = mbase + lrA, c = ks * 2 + lcA;
                ldsm4(qf[ks], sb + r * 128 + SWC(c, r));
            }
        }
        uint32_t kb = sb + 8192 + (it & 1) * 16384;
        uint32_t vb = kb + 8192;

        // ---- scores = Q @ K^T ----
        float sc[8][4];
        #pragma unroll
        for (int nt = 0; nt < 8; nt++)
            #pragma unroll
            for (int i = 0; i < 4; i++) sc[nt][i] = 0.f;
        #pragma unroll
        for (int ks = 0; ks < 4; ks++) {
            uint32_t kf[4][4];
            #pragma unroll
            for (int p = 0; p < 4; p++) {
                int r = p * 16 + lrB, c = ks * 2 + lcB;
                ldsm4(kf[p], kb + r * 128 + SWC(c, r));
            }
            #pragma unroll
            for (int nt = 0; nt < 8; nt++)
                mma16816(sc[nt], qf[ks], kf[nt >> 1] + 2 * (nt & 1));
        }

        // ---- scale (exp2 domain) + causal mask on diagonal tile ----
        if (it == ntile - 1) {
            #pragma unroll
            for (int nt = 0; nt < 8; nt++) {
                int kc = it * 64 + nt * 8 + (lane & 3) * 2;
                sc[nt][0] = (kc     <= qrow0)     ? sc[nt][0] * ATT_SCALE : -1e30f;
                sc[nt][1] = (kc + 1 <= qrow0)     ? sc[nt][1] * ATT_SCALE : -1e30f;
                sc[nt][2] = (kc     <= qrow0 + 8) ? sc[nt][2] * ATT_SCALE : -1e30f;
                sc[nt][3] = (kc + 1 <= qrow0 + 8) ? sc[nt][3] * ATT_SCALE : -1e30f;
            }
        } else {
            #pragma unroll
            for (int nt = 0; nt < 8; nt++) {
                sc[nt][0] *= ATT_SCALE; sc[nt][1] *= ATT_SCALE;
                sc[nt][2] *= ATT_SCALE; sc[nt][3] *= ATT_SCALE;
            }
        }

        // ---- online softmax (tile-granular, exp2) ----
        float mx0 = sc[0][0], mx1 = sc[0][2];
        #pragma unroll
        for (int nt = 0; nt < 8; nt++) {
            mx0 = fmaxf(mx0, fmaxf(sc[nt][0], sc[nt][1]));
            mx1 = fmaxf(mx1, fmaxf(sc[nt][2], sc[nt][3]));
        }
        mx0 = fmaxf(mx0, __shfl_xor_sync(0xffffffffu, mx0, 1));
        mx0 = fmaxf(mx0, __shfl_xor_sync(0xffffffffu, mx0, 2));
        mx1 = fmaxf(mx1, __shfl_xor_sync(0xffffffffu, mx1, 1));
        mx1 = fmaxf(mx1, __shfl_xor_sync(0xffffffffu, mx1, 2));
        float m0n = fmaxf(m0, mx0), m1n = fmaxf(m1, mx1);
        float a0 = fexp2(m0 - m0n), a1 = fexp2(m1 - m1n);
        m0 = m0n; m1 = m1n;

        float s0 = 0.f, s1 = 0.f;
        uint32_t pf[4][4];
        #pragma unroll
        for (int nt = 0; nt < 8; nt++) {
            float p0 = fexp2(sc[nt][0] - m0);
            float p1 = fexp2(sc[nt][1] - m0);
            float p2 = fexp2(sc[nt][2] - m1);
            float p3 = fexp2(sc[nt][3] - m1);
            s0 += p0 + p1; s1 += p2 + p3;
            __half2 h01 = __floats2half2_rn(p0, p1);
            __half2 h23 = __floats2half2_rn(p2, p3);
            pf[nt >> 1][(nt & 1) * 2 + 0] = *(uint32_t*)&h01;
            pf[nt >> 1][(nt & 1) * 2 + 1] = *(uint32_t*)&h23;
        }
        l0 = l0 * a0 + s0;
        l1 = l1 * a1 + s1;
        #pragma unroll
        for (int nt = 0; nt < 8; nt++) {
            oacc[nt][0] *= a0; oacc[nt][1] *= a0;
            oacc[nt][2] *= a1; oacc[nt][3] *= a1;
        }

        // ---- O += P @ V ----
        #pragma unroll
        for (int ks = 0; ks < 4; ks++) {
            uint32_t vf[4][4];
            #pragma unroll
            for (int j = 0; j < 4; j++) {
                int r = ks * 16 + ((lane >> 3) & 1) * 8 + (lane & 7);
                int c = j * 2 + (lane >> 4);
                ldsm4t(vf[j], vb + r * 128 + SWC(c, r));
            }
            #pragma unroll
            for (int j = 0; j < 4; j++) {
                mma16816(oacc[2 * j],     pf[ks], vf[j]);
                mma16816(oacc[2 * j + 1], pf[ks], vf[j] + 2);
            }
        }
        __syncthreads();
    }

    l0 += __shfl_xor_sync(0xffffffffu, l0, 1);
    l0 += __shfl_xor_sync(0xffffffffu, l0, 2);
    l1 += __shfl_xor_sync(0xffffffffu, l1, 1);
    l1 += __shfl_xor_sync(0xffffffffu, l1, 2);
    float inv0 = 1.0f / l0, inv1 = 1.0f / l1;
    #pragma unroll
    for (int nt = 0; nt < 8; nt++) {
        int cc = h * 64 + nt * 8 + (lane & 3) * 2;
        *(__half2*)(o + (size_t)qrow0 * DMODEL + cc) =
            __floats2half2_rn(oacc[nt][0] * inv0, oacc[nt][1] * inv0);
        *(__half2*)(o + (size_t)(qrow0 + 8) * DMODEL + cc) =
            __floats2half2_rn(oacc[nt][2] * inv1, oacc[nt][3] * inv1);
    }
}

// ---------------- host orchestration ----------------
extern "C" void kernel_launch(void* const* d_in, const int* in_sizes, int n_in,
                              void* d_out, int out_size)
{
    const int*   idx    = (const int*)  d_in[0];
    const float* temb   = (const float*)d_in[1];
    const float* pe     = (const float*)d_in[2];
    const float* qkv_w  = (const float*)d_in[3];
    const float* qkv_b  = (const float*)d_in[4];
    const float* out_w  = (const float*)d_in[5];
    const float* out_b  = (const float*)d_in[6];
    const float* ln1_s  = (const float*)d_in[7];
    const float* ln1_b  = (const float*)d_in[8];
    const float* ln2_s  = (const float*)d_in[9];
    const float* ln2_b  = (const float*)d_in[10];
    const float* w1     = (const float*)d_in[11];
    const float* b1     = (const float*)d_in[12];
    const float* w2     = (const float*)d_in[13];
    const float* b2     = (const float*)d_in[14];
    float* out = (float*)d_out;

    float* x;
    __half *hbuf, *qkvb, *att, *ffn, *wt;
    cudaGetSymbolAddress((void**)&x,    g_x);
    cudaGetSymbolAddress((void**)&hbuf, g_h);
    cudaGetSymbolAddress((void**)&qkvb, g_qkv);
    cudaGetSymbolAddress((void**)&att,  g_att);
    cudaGetSymbolAddress((void**)&ffn,  g_ffn);
    cudaGetSymbolAddress((void**)&wt,   g_wt);

    constexpr int SMB128 = (64 + 128) * 128 * 2;   // 49152
    constexpr int SMB64  = (64 + 64) * 128 * 2;    // 32768
    constexpr int SMATT  = 8192 + 2 * 16384;       // 40960
    cudaFuncSetAttribute(hgemm_kernel<128, 0>, cudaFuncAttributeMaxDynamicSharedMemorySize, SMB128);
    cudaFuncSetAttribute(hgemm_kernel<128, 1>, cudaFuncAttributeMaxDynamicSharedMemorySize, SMB128);
    cudaFuncSetAttribute(hgemm_kernel<64, 2>,  cudaFuncAttributeMaxDynamicSharedMemorySize, SMB64);
    cudaFuncSetAttribute(fattn_kernel,         cudaFuncAttributeMaxDynamicSharedMemorySize, SMATT);

    wconv_all_kernel<<<2 * 6912, dim3(32, 8)>>>(qkv_w, out_w, w1, w2, wt);
    embed_ln_kernel<<<S_LEN, 256>>>(idx, temb, pe, ln1_s, ln1_b, x, hbuf);

    for (int l = 0; l < NLAYER; l++) {
        __half* wl = wt + (size_t)l * WT_LAYER;
        const float* lqkv_b = qkv_b + (size_t)l * 3 * DMODEL;
        const float* lout_b = out_b + (size_t)l * DMODEL;
        const float* lb1    = b1 + (size_t)l * FFN;
        const float* lb2    = b2 + (size_t)l * DMODEL;

        if (l > 0)
            ln_kernel<<<S_LEN, 256>>>(x, ln1_s + l * DMODEL, ln1_b + l * DMODEL, hbuf);
        hgemm_kernel<128, 0><<<dim3(3 * DMODEL / 128, S_LEN / 64), 256, SMB128>>>(
            hbuf, wl + OQKV, lqkv_b, nullptr, qkvb, S_LEN, 3 * DMODEL, DMODEL);
        fattn_kernel<<<dim3(S_LEN / 64, NHEAD), 128, SMATT>>>(qkvb, att);
        hgemm_kernel<64, 2><<<dim3(DMODEL / 64, S_LEN / 64), 128, SMB64>>>(
            att, wl + OOUT, lout_b, x, x, S_LEN, DMODEL, DMODEL);
        ln_kernel<<<S_LEN, 256>>>(x, ln2_s + l * DMODEL, ln2_b + l * DMODEL, hbuf);
        hgemm_kernel<128, 1><<<dim3(FFN / 128, S_LEN / 64), 256, SMB128>>>(
            hbuf, wl + OW1, lb1, nullptr, ffn, S_LEN, FFN, DMODEL);
        float* dst = (l == NLAYER - 1) ? out : x;
        hgemm_kernel<64, 2><<<dim3(DMODEL / 64, S_LEN / 64), 128, SMB64>>>(
            ffn, wl + OW2, lb2, x, dst, S_LEN, DMODEL, FFN);
    }
}